// round 7
// baseline (speedup 1.0000x reference)
#include <cuda_runtime.h>
#include <stdint.h>

// Problem constants (fixed by the reference):
//   B=16, L=512, NSESS=4, S=512, H=512
// Logical inputs (identified by element count, order-invariant):
//   session_repre        (B,4,S,H) f32        -> 8,388,608 elems (unique)
//   state_transition_mat (B,L,5)   int64/int32 -> 40,960 elems (unique)
// Output: (B, L, 5, H) f32
//
// out[b,l,j,:] = session_repre[b, sess_idx[j], stm[b,l,j]-1, :]
//   with sess_idx = {3,0,1,2,3}
// out[b,l,0,:] = mean_{j=0..3} gathered[b,l,j,:]
//
// R7: L2 residency control, restructured for sm_103a's 256-bit evict_last
// requirement. Gather reads = ld.global.nc.L2::evict_last.v8.b32 (pins the
// 64MB table in 126MB L2 across graph replays); output = st.global.cs
// (evict-first streaming). 64 threads per (b,l), 32B per thread.

#define B_DIM 16
#define L_DIM 512
#define S_DIM 512
#define H_DIM 512
#define PAIRS_PER_BLOCK 4   // 4 (b,l) pairs per 256-thread block (64 thr each)

struct f8 { float v[8]; };

__device__ __forceinline__ f8 ld_evict_last_32B(const float* p) {
    f8 r;
    asm volatile(
        "ld.global.nc.L2::evict_last.v8.b32 {%0,%1,%2,%3,%4,%5,%6,%7}, [%8];"
        : "=f"(r.v[0]), "=f"(r.v[1]), "=f"(r.v[2]), "=f"(r.v[3]),
          "=f"(r.v[4]), "=f"(r.v[5]), "=f"(r.v[6]), "=f"(r.v[7])
        : "l"(p));
    return r;
}

__device__ __forceinline__ void st_streaming_32B(float* p, const f8& r) {
    asm volatile("st.global.cs.v4.f32 [%0], {%1,%2,%3,%4};"
                 :: "l"(p), "f"(r.v[0]), "f"(r.v[1]), "f"(r.v[2]), "f"(r.v[3])
                 : "memory");
    asm volatile("st.global.cs.v4.f32 [%0], {%1,%2,%3,%4};"
                 :: "l"(p + 4), "f"(r.v[4]), "f"(r.v[5]), "f"(r.v[6]), "f"(r.v[7])
                 : "memory");
}

__global__ void __launch_bounds__(256, 4)
state_matrix_encoder_kernel(const float* __restrict__ sess,
                            const int* __restrict__ stm32,
                            float* __restrict__ out) {
    const int bl = blockIdx.x * PAIRS_PER_BLOCK + (threadIdx.x >> 6); // (b,l)
    const int b  = bl >> 9;                 // / L_DIM
    const int t  = threadIdx.x & 63;        // 0..63, 8 floats (32B) each
    const int e  = t * 8;                   // float offset within a row

    // Index dtype detection from data: values are in [1,512] (nonzero).
    // int64 LE layout -> stm32[1] == high word of idx0 == 0.
    // int32 layout    -> stm32[1] == idx1 in [1,512] != 0.
    const int stride = (stm32[1] == 0) ? 2 : 1;   // int32 words per index

    const int base = bl * 5 * stride;
    const int p0 = stm32[base + 0 * stride] - 1;
    const int p1 = stm32[base + 1 * stride] - 1;
    const int p2 = stm32[base + 2 * stride] - 1;
    const int p3 = stm32[base + 3 * stride] - 1;
    const int p4 = stm32[base + 4 * stride] - 1;

    // session_repre row start (floats): ((b*4 + s)*S + pos) * H
    const size_t bbase = (size_t)b * 4 * S_DIM;
    const f8 g0 = ld_evict_last_32B(sess + (bbase + (size_t)3 * S_DIM + p0) * H_DIM + e);
    const f8 g1 = ld_evict_last_32B(sess + (bbase + (size_t)0 * S_DIM + p1) * H_DIM + e);
    const f8 g2 = ld_evict_last_32B(sess + (bbase + (size_t)1 * S_DIM + p2) * H_DIM + e);
    const f8 g3 = ld_evict_last_32B(sess + (bbase + (size_t)2 * S_DIM + p3) * H_DIM + e);
    const f8 g4 = ld_evict_last_32B(sess + (bbase + (size_t)3 * S_DIM + p4) * H_DIM + e);

    f8 pooled;
    #pragma unroll
    for (int i = 0; i < 8; i++)
        pooled.v[i] = (g0.v[i] + g1.v[i] + g2.v[i] + g3.v[i]) * 0.25f;

    // Streaming (evict-first) stores: output never re-read; keep it from
    // displacing session_repre in L2.
    float* o = out + (size_t)bl * 5 * H_DIM + e;
    st_streaming_32B(o + 0 * H_DIM, pooled);
    st_streaming_32B(o + 1 * H_DIM, g1);
    st_streaming_32B(o + 2 * H_DIM, g2);
    st_streaming_32B(o + 3 * H_DIM, g3);
    st_streaming_32B(o + 4 * H_DIM, g4);
}

extern "C" void kernel_launch(void* const* d_in, const int* in_sizes, int n_in,
                              void* d_out, int out_size) {
    // Order-invariant input identification by element count.
    const float* sess  = nullptr;
    const int*   stm32 = nullptr;
    for (int i = 0; i < n_in; i++) {
        if (in_sizes[i] == B_DIM * 4 * S_DIM * H_DIM) sess  = (const float*)d_in[i];
        else if (in_sizes[i] == B_DIM * L_DIM * 5)    stm32 = (const int*)d_in[i];
    }

    state_matrix_encoder_kernel<<<(B_DIM * L_DIM) / PAIRS_PER_BLOCK, 256>>>(
        sess, stm32, (float*)d_out);
}

// round 8
// speedup vs baseline: 1.2545x; 1.2545x over previous
#include <cuda_runtime.h>
#include <stdint.h>

// Problem constants (fixed by the reference):
//   B=16, L=512, NSESS=4, S=512, H=512
// Logical inputs (identified by element count, order-invariant):
//   session_repre        (B,4,S,H) f32        -> 8,388,608 elems (unique)
//   state_transition_mat (B,L,5)   int64/int32 -> 40,960 elems (unique)
// Output: (B, L, 5, H) f32
//
// out[b,l,j,:] = session_repre[b, sess_idx[j], stm[b,l,j]-1, :]
//   with sess_idx = {3,0,1,2,3}
// out[b,l,0,:] = mean_{j=0..3} gathered[b,l,j,:]
//
// R8: best-known geometry (R3) + single-LDG vectorized index fetch.
// Established across R2-R7: the kernel sits on the DRAM write-drain floor
// (~84MB output at ~4.3TB/s effective write bw ≈ 19.5us); all exotic paths
// (TMA, evict hints, v8) are neutral or worse. This variant minimizes the
// per-CTA dependent-latency chain: indices arrive in 1-2 loads, gathers
// issue back-to-back with full MLP, stores stream out evict-first.

#define B_DIM 16
#define L_DIM 512
#define S_DIM 512
#define H_DIM 512
#define H4    (H_DIM / 4)   // 128 float4 per row
#define PAIRS_PER_BLOCK 2   // 2 (b,l) pairs per 256-thread block

__global__ void __launch_bounds__(256)
state_matrix_encoder_kernel(const float4* __restrict__ sess,
                            const int* __restrict__ stm32,
                            float4* __restrict__ out) {
    const int bl = blockIdx.x * PAIRS_PER_BLOCK + (threadIdx.x >> 7); // (b,l)
    const int b  = bl >> 9;                 // / L_DIM
    const int t  = threadIdx.x & 127;       // 0..127 (one float4 each)

    // Index dtype detection from data: values are in [1,512] (nonzero).
    // int64 LE layout -> word[1] == high word of idx0 == 0.
    // int32 layout    -> word[1] == idx1 in [1,512] != 0.
    int p0, p1, p2, p3, p4;
    if (__ldg(&stm32[1]) == 0) {
        // int64 indices: 5 * 8B = 40B per (b,l), 8B-aligned. Two 16B loads
        // (words 0..3, 4..7) + one 8B load (words 8..9).
        const int4* q = (const int4*)(stm32 + bl * 10);
        const int4 a = __ldg(&q[0]);            // idx0.lo, idx0.hi, idx1.lo, idx1.hi
        const int4 c = __ldg(&q[1]);            // idx2.lo, idx2.hi, idx3.lo, idx3.hi
        const int2 e = __ldg((const int2*)(stm32 + bl * 10 + 8)); // idx4.lo, idx4.hi
        p0 = a.x - 1; p1 = a.z - 1; p2 = c.x - 1; p3 = c.z - 1; p4 = e.x - 1;
    } else {
        // int32 indices: 5 * 4B = 20B per (b,l), 4B-aligned only -> scalar.
        const int* q = stm32 + bl * 5;
        p0 = __ldg(&q[0]) - 1; p1 = __ldg(&q[1]) - 1; p2 = __ldg(&q[2]) - 1;
        p3 = __ldg(&q[3]) - 1; p4 = __ldg(&q[4]) - 1;
    }

    // session_repre row base (in rows): (b*4 + s)*S + pos
    const size_t bbase = (size_t)b * 4 * S_DIM;
    const float4 g0 = __ldg(&sess[(bbase + (size_t)3 * S_DIM + p0) * H4 + t]);
    const float4 g1 = __ldg(&sess[(bbase + (size_t)0 * S_DIM + p1) * H4 + t]);
    const float4 g2 = __ldg(&sess[(bbase + (size_t)1 * S_DIM + p2) * H4 + t]);
    const float4 g3 = __ldg(&sess[(bbase + (size_t)2 * S_DIM + p3) * H4 + t]);
    const float4 g4 = __ldg(&sess[(bbase + (size_t)3 * S_DIM + p4) * H4 + t]);

    float4 pooled;
    pooled.x = (g0.x + g1.x + g2.x + g3.x) * 0.25f;
    pooled.y = (g0.y + g1.y + g2.y + g3.y) * 0.25f;
    pooled.z = (g0.z + g1.z + g2.z + g3.z) * 0.25f;
    pooled.w = (g0.w + g1.w + g2.w + g3.w) * 0.25f;

    // Streaming (evict-first) stores: output is never re-read; don't let the
    // 84MB write stream displace session_repre from L2.
    float4* o = out + (size_t)bl * 5 * H4;
    __stcs(o + 0 * H4 + t, pooled);
    __stcs(o + 1 * H4 + t, g1);
    __stcs(o + 2 * H4 + t, g2);
    __stcs(o + 3 * H4 + t, g3);
    __stcs(o + 4 * H4 + t, g4);
}

extern "C" void kernel_launch(void* const* d_in, const int* in_sizes, int n_in,
                              void* d_out, int out_size) {
    // Order-invariant input identification by element count.
    const float4* sess  = nullptr;
    const int*    stm32 = nullptr;
    for (int i = 0; i < n_in; i++) {
        if (in_sizes[i] == B_DIM * 4 * S_DIM * H_DIM) sess  = (const float4*)d_in[i];
        else if (in_sizes[i] == B_DIM * L_DIM * 5)    stm32 = (const int*)d_in[i];
    }

    state_matrix_encoder_kernel<<<(B_DIM * L_DIM) / PAIRS_PER_BLOCK, 256>>>(
        sess, stm32, (float4*)d_out);
}

// round 9
// speedup vs baseline: 1.3412x; 1.0691x over previous
#include <cuda_runtime.h>
#include <stdint.h>

// Problem constants (fixed by the reference):
//   B=16, L=512, NSESS=4, S=512, H=512
// Logical inputs (identified by element count, order-invariant):
//   session_repre        (B,4,S,H) f32        -> 8,388,608 elems (unique)
//   state_transition_mat (B,L,5)   int64/int32 -> 40,960 elems (unique)
// Output: (B, L, 5, H) f32
//
// out[b,l,j,:] = session_repre[b, sess_idx[j], stm[b,l,j]-1, :]
//   with sess_idx = {3,0,1,2,3}
// out[b,l,0,:] = mean_{j=0..3} gathered[b,l,j,:]
//
// R9: persistent grid-stride kernel, single wave (1184 CTAs = 148 SM x 8).
// R2-R8 established: all data-path variants (STG/stcs/TMA/v8) pin at
// 19.5-20.1us with NOTHING saturated (DRAM 45%, L2 43%, issue 18%) ->
// exposed latency + wave quantization, not a bandwidth floor. The loop
// overlaps iteration i's store drain with iteration i+1's index/gather
// loads, removing per-CTA cold starts and the ~3.5-wave transitions.

#define B_DIM 16
#define L_DIM 512
#define S_DIM 512
#define H_DIM 512
#define H4    (H_DIM / 4)   // 128 float4 per row
#define NPAIRS (B_DIM * L_DIM)   // 8192
#define GRID_CTAS (148 * 8)      // one full wave at 256 thr (2048 thr/SM)

__global__ void __launch_bounds__(256)
state_matrix_encoder_kernel(const float4* __restrict__ sess,
                            const int* __restrict__ stm32,
                            float4* __restrict__ out) {
    const int group0  = blockIdx.x * 2 + (threadIdx.x >> 7); // (b,l) group id
    const int ngroups = GRID_CTAS * 2;
    const int t       = threadIdx.x & 127;   // 0..127 (one float4 per row)

    // Index dtype detection from data: values are in [1,512] (nonzero).
    // int64 LE layout -> word[1] == high word of idx0 == 0.
    // int32 layout    -> word[1] == idx1 in [1,512] != 0.
    const bool idx64 = (__ldg(&stm32[1]) == 0);

    for (int bl = group0; bl < NPAIRS; bl += ngroups) {
        const int b = bl >> 9;               // / L_DIM

        int p0, p1, p2, p3, p4;
        if (idx64) {
            // int64 indices: 5*8B = 40B per (b,l), 8B-aligned.
            const int4 a = __ldg((const int4*)(stm32 + bl * 10));
            const int4 c = __ldg((const int4*)(stm32 + bl * 10 + 4));
            const int2 e = __ldg((const int2*)(stm32 + bl * 10 + 8));
            p0 = a.x - 1; p1 = a.z - 1; p2 = c.x - 1; p3 = c.z - 1; p4 = e.x - 1;
        } else {
            const int* q = stm32 + bl * 5;
            p0 = __ldg(&q[0]) - 1; p1 = __ldg(&q[1]) - 1; p2 = __ldg(&q[2]) - 1;
            p3 = __ldg(&q[3]) - 1; p4 = __ldg(&q[4]) - 1;
        }

        // session_repre row base (in rows): (b*4 + s)*S + pos
        const size_t bbase = (size_t)b * 4 * S_DIM;
        const float4 g0 = __ldg(&sess[(bbase + (size_t)3 * S_DIM + p0) * H4 + t]);
        const float4 g1 = __ldg(&sess[(bbase + (size_t)0 * S_DIM + p1) * H4 + t]);
        const float4 g2 = __ldg(&sess[(bbase + (size_t)1 * S_DIM + p2) * H4 + t]);
        const float4 g3 = __ldg(&sess[(bbase + (size_t)2 * S_DIM + p3) * H4 + t]);
        const float4 g4 = __ldg(&sess[(bbase + (size_t)3 * S_DIM + p4) * H4 + t]);

        float4 pooled;
        pooled.x = (g0.x + g1.x + g2.x + g3.x) * 0.25f;
        pooled.y = (g0.y + g1.y + g2.y + g3.y) * 0.25f;
        pooled.z = (g0.z + g1.z + g2.z + g3.z) * 0.25f;
        pooled.w = (g0.w + g1.w + g2.w + g3.w) * 0.25f;

        // Streaming (evict-first) stores: output is never re-read; keep the
        // 84MB write stream from displacing session_repre in L2.
        float4* o = out + (size_t)bl * 5 * H4;
        __stcs(o + 0 * H4 + t, pooled);
        __stcs(o + 1 * H4 + t, g1);
        __stcs(o + 2 * H4 + t, g2);
        __stcs(o + 3 * H4 + t, g3);
        __stcs(o + 4 * H4 + t, g4);
    }
}

extern "C" void kernel_launch(void* const* d_in, const int* in_sizes, int n_in,
                              void* d_out, int out_size) {
    // Order-invariant input identification by element count.
    const float4* sess  = nullptr;
    const int*    stm32 = nullptr;
    for (int i = 0; i < n_in; i++) {
        if (in_sizes[i] == B_DIM * 4 * S_DIM * H_DIM) sess  = (const float4*)d_in[i];
        else if (in_sizes[i] == B_DIM * L_DIM * 5)    stm32 = (const int*)d_in[i];
    }

    state_matrix_encoder_kernel<<<GRID_CTAS, 256>>>(sess, stm32, (float4*)d_out);
}